// round 1
// baseline (speedup 1.0000x reference)
#include <cuda_runtime.h>

#define D_IN   64
#define D_HID  128
#define D_OUT  64
#define MAX_NODES 100000
#define NPB    64   // nodes per block in main kernel

// Scratch (no allocations allowed in kernel_launch)
__device__ int   g_deg[MAX_NODES];
__device__ float g_W12[D_IN * D_OUT];
__device__ float g_bW[D_OUT];
__device__ int   g_is64;

// ---------------------------------------------------------------------------
// Detect whether edge_index is int64 (odd 32-bit words all zero) or int32.
// Values are in [0, 100000), nonnegative, little-endian.
__global__ void detect_dtype_kernel(const int* __restrict__ p) {
    int is64 = 1;
    #pragma unroll
    for (int i = 1; i < 64; i += 2)
        if (p[i] != 0) is64 = 0;
    g_is64 = is64;
}

// ---------------------------------------------------------------------------
__global__ void zero_deg_kernel(int n) {
    int i = blockIdx.x * blockDim.x + threadIdx.x;
    if (i < n) g_deg[i] = 0;
}

// Degree histogram over edge_index[1] (the dst row).
__global__ void hist_kernel(const void* __restrict__ edge_index, int E) {
    int i = blockIdx.x * blockDim.x + threadIdx.x;
    if (i >= E) return;
    int d;
    if (g_is64) {
        const long long* p = (const long long*)edge_index;
        d = (int)p[(size_t)E + i];
    } else {
        const int* p = (const int*)edge_index;
        d = p[(size_t)E + i];
    }
    atomicAdd(&g_deg[d], 1);
}

// ---------------------------------------------------------------------------
// Precompute W12 = W1 @ W2  ([64,128]@[128,64]) and bW = b1 @ W2.
// Blocks 0..63 compute row i of W12; block 64 computes bW.
__global__ void prep_weights_kernel(const float* __restrict__ W1,
                                    const float* __restrict__ b1,
                                    const float* __restrict__ W2) {
    int j = threadIdx.x;  // 0..63 output column
    if (blockIdx.x < D_IN) {
        const float* w1r = W1 + (size_t)blockIdx.x * D_HID;
        float acc = 0.f;
        #pragma unroll 16
        for (int k = 0; k < D_HID; ++k)
            acc = fmaf(w1r[k], W2[(size_t)k * D_OUT + j], acc);
        g_W12[blockIdx.x * D_OUT + j] = acc;
    } else {
        float acc = 0.f;
        #pragma unroll 16
        for (int k = 0; k < D_HID; ++k)
            acc = fmaf(b1[k], W2[(size_t)k * D_OUT + j], acc);
        g_bW[j] = acc;
    }
}

// ---------------------------------------------------------------------------
// Main fused kernel: out[n] = (1+deg[n]) * (x[n] @ W12 + bW) + b2
// Block = 256 threads handles 64 nodes. Thread (nl = tid/4, q = tid%4)
// computes output columns [q*16, q*16+16) for node nl.
__global__ __launch_bounds__(256) void gnn_main_kernel(
    const float* __restrict__ x,
    const float* __restrict__ b2,
    float* __restrict__ out,
    int n_nodes)
{
    __shared__ float  xs[NPB][D_IN + 1];            // +1 pad: conflict-free
    __shared__ float4 w12[D_IN][D_OUT / 4];         // row-major, vectorized
    __shared__ float  bw_s[D_OUT];
    __shared__ float  b2_s[D_OUT];

    const int base = blockIdx.x * NPB;
    const int remaining = n_nodes - base;

    // Stage W12 (4096 floats = 1024 float4)
    for (int i = threadIdx.x; i < D_IN * D_OUT / 4; i += 256)
        ((float4*)w12)[i] = ((const float4*)g_W12)[i];
    if (threadIdx.x < D_OUT) {
        bw_s[threadIdx.x] = g_bW[threadIdx.x];
        b2_s[threadIdx.x] = b2[threadIdx.x];
    }
    // Stage x tile (coalesced)
    for (int i = threadIdx.x; i < NPB * D_IN; i += 256) {
        int nl = i >> 6, c = i & 63;
        xs[nl][c] = (nl < remaining) ? x[(size_t)(base + nl) * D_IN + c] : 0.f;
    }
    __syncthreads();

    const int nl = threadIdx.x >> 2;
    const int q  = threadIdx.x & 3;
    if (nl >= remaining) return;

    float4 a0 = {0.f,0.f,0.f,0.f}, a1 = a0, a2 = a0, a3 = a0;

    #pragma unroll 16
    for (int k = 0; k < D_IN; ++k) {
        const float xv = xs[nl][k];
        float4 w;
        w = w12[k][q * 4 + 0];
        a0.x = fmaf(xv, w.x, a0.x); a0.y = fmaf(xv, w.y, a0.y);
        a0.z = fmaf(xv, w.z, a0.z); a0.w = fmaf(xv, w.w, a0.w);
        w = w12[k][q * 4 + 1];
        a1.x = fmaf(xv, w.x, a1.x); a1.y = fmaf(xv, w.y, a1.y);
        a1.z = fmaf(xv, w.z, a1.z); a1.w = fmaf(xv, w.w, a1.w);
        w = w12[k][q * 4 + 2];
        a2.x = fmaf(xv, w.x, a2.x); a2.y = fmaf(xv, w.y, a2.y);
        a2.z = fmaf(xv, w.z, a2.z); a2.w = fmaf(xv, w.w, a2.w);
        w = w12[k][q * 4 + 3];
        a3.x = fmaf(xv, w.x, a3.x); a3.y = fmaf(xv, w.y, a3.y);
        a3.z = fmaf(xv, w.z, a3.z); a3.w = fmaf(xv, w.w, a3.w);
    }

    const int node = base + nl;
    const float s = 1.0f + (float)g_deg[node];
    const int c0 = q * 16;

    float4 r;
    float4* op = (float4*)(out + (size_t)node * D_OUT + c0);

    r.x = fmaf(s, a0.x + bw_s[c0 +  0], b2_s[c0 +  0]);
    r.y = fmaf(s, a0.y + bw_s[c0 +  1], b2_s[c0 +  1]);
    r.z = fmaf(s, a0.z + bw_s[c0 +  2], b2_s[c0 +  2]);
    r.w = fmaf(s, a0.w + bw_s[c0 +  3], b2_s[c0 +  3]);
    op[0] = r;
    r.x = fmaf(s, a1.x + bw_s[c0 +  4], b2_s[c0 +  4]);
    r.y = fmaf(s, a1.y + bw_s[c0 +  5], b2_s[c0 +  5]);
    r.z = fmaf(s, a1.z + bw_s[c0 +  6], b2_s[c0 +  6]);
    r.w = fmaf(s, a1.w + bw_s[c0 +  7], b2_s[c0 +  7]);
    op[1] = r;
    r.x = fmaf(s, a2.x + bw_s[c0 +  8], b2_s[c0 +  8]);
    r.y = fmaf(s, a2.y + bw_s[c0 +  9], b2_s[c0 +  9]);
    r.z = fmaf(s, a2.z + bw_s[c0 + 10], b2_s[c0 + 10]);
    r.w = fmaf(s, a2.w + bw_s[c0 + 11], b2_s[c0 + 11]);
    op[2] = r;
    r.x = fmaf(s, a3.x + bw_s[c0 + 12], b2_s[c0 + 12]);
    r.y = fmaf(s, a3.y + bw_s[c0 + 13], b2_s[c0 + 13]);
    r.z = fmaf(s, a3.z + bw_s[c0 + 14], b2_s[c0 + 14]);
    r.w = fmaf(s, a3.w + bw_s[c0 + 15], b2_s[c0 + 15]);
    op[3] = r;
}

// ---------------------------------------------------------------------------
extern "C" void kernel_launch(void* const* d_in, const int* in_sizes, int n_in,
                              void* d_out, int out_size) {
    const float* x   = (const float*)d_in[0];
    const void*  ei  = d_in[1];                 // edge_index [2, E], int32 or int64
    const float* W1  = (const float*)d_in[2];
    const float* b1  = (const float*)d_in[3];
    const float* W2  = (const float*)d_in[4];
    const float* b2  = (const float*)d_in[5];
    float* out = (float*)d_out;

    const int n = in_sizes[0] / D_IN;   // 100000
    const int E = in_sizes[1] / 2;      // 1000000

    detect_dtype_kernel<<<1, 1>>>((const int*)ei);
    zero_deg_kernel<<<(n + 255) / 256, 256>>>(n);
    hist_kernel<<<(E + 255) / 256, 256>>>(ei, E);
    prep_weights_kernel<<<D_IN + 1, D_OUT>>>(W1, b1, W2);
    gnn_main_kernel<<<(n + NPB - 1) / NPB, 256>>>(x, b2, out, n);
}

// round 2
// speedup vs baseline: 1.8735x; 1.8735x over previous
#include <cuda_runtime.h>

#define D_IN   64
#define D_OUT  64
#define D_HID  128
#define MAX_NODES 100000
#define NPB    256                 // nodes per block (== threads per block)
#define XS_STRIDE 65               // padded row stride for xs (conflict-free)

// Scratch (no allocations allowed)
__device__ int   g_deg[MAX_NODES];
__device__ float g_W12[D_IN * D_OUT];
__device__ float g_bW[D_OUT];
__device__ int   g_is64;

// ---------------------------------------------------------------------------
// Packed f32x2 helpers (sm_103a FFMA2 path)
__device__ __forceinline__ unsigned long long fma2(unsigned long long a,
                                                   unsigned long long b,
                                                   unsigned long long c) {
    unsigned long long d;
    asm("fma.rn.f32x2 %0, %1, %2, %3;" : "=l"(d) : "l"(a), "l"(b), "l"(c));
    return d;
}
__device__ __forceinline__ unsigned long long bcast2(float x) {
    unsigned int xi = __float_as_uint(x);
    unsigned long long d;
    asm("mov.b64 %0, {%1, %1};" : "=l"(d) : "r"(xi));
    return d;
}
__device__ __forceinline__ void unpack2(unsigned long long v, float& lo, float& hi) {
    unsigned int a, b;
    asm("mov.b64 {%0, %1}, %2;" : "=r"(a), "=r"(b) : "l"(v));
    lo = __uint_as_float(a); hi = __uint_as_float(b);
}

// ---------------------------------------------------------------------------
// Fused setup: zero g_deg, detect edge dtype, precompute W12 = W1@W2, bW = b1@W2.
// Blocks [0, ZB): zero. Block ZB: dtype detect. Blocks [ZB+1, ZB+1+65): prep.
__global__ __launch_bounds__(256) void setup_kernel(
    const int* __restrict__ ei32,
    const float* __restrict__ W1,
    const float* __restrict__ b1,
    const float* __restrict__ W2,
    int n, int ZB)
{
    const int bid = blockIdx.x, tid = threadIdx.x;

    if (bid < ZB) {                     // zero degree array
        int i = bid * 256 + tid;
        if (i < n) g_deg[i] = 0;
        return;
    }
    if (bid == ZB) {                    // int64-vs-int32 detection
        if (tid == 0) {
            int is64 = 1;
            #pragma unroll
            for (int i = 1; i < 64; i += 2)
                if (ei32[i] != 0) is64 = 0;
            g_is64 = is64;
        }
        return;
    }

    // prep: r in [0,64) -> row r of W12; r == 64 -> bW
    const int r  = bid - (ZB + 1);
    const int j  = tid & 63;            // output column
    const int kc = tid >> 6;            // k-chunk 0..3
    const float* src = (r < D_IN) ? (W1 + (size_t)r * D_HID) : b1;

    float a = 0.f;
    #pragma unroll 8
    for (int k = kc * 32; k < kc * 32 + 32; ++k)
        a = fmaf(src[k], W2[(size_t)k * D_OUT + j], a);

    __shared__ float red[4][64];
    red[kc][j] = a;
    __syncthreads();
    if (kc == 0) {
        float v = red[0][j] + red[1][j] + red[2][j] + red[3][j];
        if (r < D_IN) g_W12[r * D_OUT + j] = v;
        else          g_bW[j] = v;
    }
}

// ---------------------------------------------------------------------------
// Degree histogram, 4 edges per thread, vectorized reads.
__global__ __launch_bounds__(256) void hist_kernel(const void* __restrict__ ei, int E) {
    const int i = (blockIdx.x * 256 + threadIdx.x) * 4;
    if (i >= E) return;
    if (g_is64) {
        const unsigned long long* p = (const unsigned long long*)ei + E;  // dst row
        if (i + 4 <= E) {
            ulonglong2 a = ((const ulonglong2*)(p + i))[0];
            ulonglong2 b = ((const ulonglong2*)(p + i))[1];
            atomicAdd(&g_deg[(int)a.x], 1); atomicAdd(&g_deg[(int)a.y], 1);
            atomicAdd(&g_deg[(int)b.x], 1); atomicAdd(&g_deg[(int)b.y], 1);
        } else {
            for (int j = i; j < E; ++j) atomicAdd(&g_deg[(int)p[j]], 1);
        }
    } else {
        const int* p = (const int*)ei + E;                                 // dst row
        if (i + 4 <= E) {
            int4 v = *(const int4*)(p + i);
            atomicAdd(&g_deg[v.x], 1); atomicAdd(&g_deg[v.y], 1);
            atomicAdd(&g_deg[v.z], 1); atomicAdd(&g_deg[v.w], 1);
        } else {
            for (int j = i; j < E; ++j) atomicAdd(&g_deg[p[j]], 1);
        }
    }
}

// ---------------------------------------------------------------------------
// Main fused kernel: out[n] = (1+deg[n]) * (x[n] @ W12 + bW) + b2
// 256 threads, 256 nodes/block. Thread (g = tid>>2, q = tid&3) computes
// output cols [16q, 16q+16) for 4 nodes [4g, 4g+4) using packed f32x2 FMA.
__global__ __launch_bounds__(256) void gnn_main_kernel(
    const float* __restrict__ x,
    const float* __restrict__ b2,
    float* __restrict__ out,
    int n)
{
    extern __shared__ float smem[];
    float* xs   = smem;                          // NPB * XS_STRIDE
    float* w12  = smem + NPB * XS_STRIDE;        // 64*64
    float* bw_s = w12 + D_IN * D_OUT;            // 64
    float* b2_s = bw_s + D_OUT;                  // 64

    const int tid  = threadIdx.x;
    const int base = blockIdx.x * NPB;

    // Stage W12 (vectorized) + biases
    for (int i = tid; i < D_IN * D_OUT / 4; i += 256)
        ((float4*)w12)[i] = ((const float4*)g_W12)[i];
    if (tid < D_OUT) { bw_s[tid] = g_bW[tid]; b2_s[tid] = b2[tid]; }

    // Stage x tile: scalar, coalesced LDG, conflict-free STS (padded rows)
    #pragma unroll 4
    for (int i = tid; i < NPB * D_IN; i += 256) {
        int nl = i >> 6, c = i & 63;
        xs[nl * XS_STRIDE + c] =
            (base + nl < n) ? x[(size_t)(base + nl) * D_IN + c] : 0.f;
    }
    __syncthreads();

    const int q  = tid & 3;
    const int n0 = (tid >> 2) * 4;               // local node base (4 nodes)

    unsigned long long acc[4][8];
    #pragma unroll
    for (int i = 0; i < 4; ++i)
        #pragma unroll
        for (int j = 0; j < 8; ++j) acc[i][j] = 0ull;

    const float* wcol = w12 + q * 16;

    #pragma unroll 8
    for (int k = 0; k < D_IN; ++k) {
        const ulonglong2* wp = (const ulonglong2*)(wcol + k * D_OUT);
        ulonglong2 wa = wp[0], wb = wp[1], wc = wp[2], wd = wp[3];
        unsigned long long w[8] = {wa.x, wa.y, wb.x, wb.y, wc.x, wc.y, wd.x, wd.y};
        #pragma unroll
        for (int i = 0; i < 4; ++i) {
            unsigned long long xp = bcast2(xs[(n0 + i) * XS_STRIDE + k]);
            #pragma unroll
            for (int j = 0; j < 8; ++j) acc[i][j] = fma2(xp, w[j], acc[i][j]);
        }
    }

    // Epilogue: scale by (1+deg), add biases, vectorized store
    const int c0 = q * 16;
    #pragma unroll
    for (int i = 0; i < 4; ++i) {
        const int node = base + n0 + i;
        if (node >= n) break;
        const float s = 1.0f + (float)g_deg[node];
        float4* op = (float4*)(out + (size_t)node * D_OUT + c0);
        #pragma unroll
        for (int v = 0; v < 4; ++v) {
            float lo0, hi0, lo1, hi1;
            unpack2(acc[i][2 * v],     lo0, hi0);
            unpack2(acc[i][2 * v + 1], lo1, hi1);
            const int c = c0 + v * 4;
            float4 r;
            r.x = fmaf(s, lo0 + bw_s[c + 0], b2_s[c + 0]);
            r.y = fmaf(s, hi0 + bw_s[c + 1], b2_s[c + 1]);
            r.z = fmaf(s, lo1 + bw_s[c + 2], b2_s[c + 2]);
            r.w = fmaf(s, hi1 + bw_s[c + 3], b2_s[c + 3]);
            op[v] = r;
        }
    }
}

// ---------------------------------------------------------------------------
extern "C" void kernel_launch(void* const* d_in, const int* in_sizes, int n_in,
                              void* d_out, int out_size) {
    const float* x  = (const float*)d_in[0];
    const void*  ei = d_in[1];
    const float* W1 = (const float*)d_in[2];
    const float* b1 = (const float*)d_in[3];
    const float* W2 = (const float*)d_in[4];
    const float* b2 = (const float*)d_in[5];
    float* out = (float*)d_out;

    const int n = in_sizes[0] / D_IN;   // 100000
    const int E = in_sizes[1] / 2;      // 1000000
    const int ZB = (n + 255) / 256;     // zero blocks

    setup_kernel<<<ZB + 1 + 65, 256>>>((const int*)ei, W1, b1, W2, n, ZB);
    hist_kernel<<<(E + 1023) / 1024, 256>>>(ei, E);

    const size_t smem_bytes =
        (NPB * XS_STRIDE + D_IN * D_OUT + 2 * D_OUT) * sizeof(float);
    cudaFuncSetAttribute(gnn_main_kernel,
                         cudaFuncAttributeMaxDynamicSharedMemorySize,
                         (int)smem_bytes);
    gnn_main_kernel<<<(n + NPB - 1) / NPB, 256, smem_bytes>>>(x, b2, out, n);
}

// round 3
// speedup vs baseline: 2.4723x; 1.3196x over previous
#include <cuda_runtime.h>

#define D_IN   64
#define D_OUT  64
#define D_HID  128
#define MAX_NODES 100000
#define NPB    256                 // nodes per block in main kernel
#define XS_STRIDE 65               // padded row stride for xs
#define PREP_BLOCKS 65             // W12 rows + bW
#define EPT    8                   // edges per thread in hist

// Scratch. g_deg relies on the consume-reset invariant: it is zero-initialized
// at module load, and gnn_main_kernel resets each entry to 0 after reading it,
// so every kernel_launch call starts from an all-zero histogram.
__device__ int   g_deg[MAX_NODES];
__device__ float g_W12[D_IN * D_OUT];
__device__ float g_bW[D_OUT];

// ---------------------------------------------------------------------------
// Packed f32x2 helpers (sm_103a FFMA2 path)
__device__ __forceinline__ unsigned long long fma2(unsigned long long a,
                                                   unsigned long long b,
                                                   unsigned long long c) {
    unsigned long long d;
    asm("fma.rn.f32x2 %0, %1, %2, %3;" : "=l"(d) : "l"(a), "l"(b), "l"(c));
    return d;
}
__device__ __forceinline__ unsigned long long bcast2(float x) {
    unsigned int xi = __float_as_uint(x);
    unsigned long long d;
    asm("mov.b64 %0, {%1, %1};" : "=l"(d) : "r"(xi));
    return d;
}
__device__ __forceinline__ void unpack2(unsigned long long v, float& lo, float& hi) {
    unsigned int a, b;
    asm("mov.b64 {%0, %1}, %2;" : "=r"(a), "=r"(b) : "l"(v));
    lo = __uint_as_float(a); hi = __uint_as_float(b);
}

// ---------------------------------------------------------------------------
// K1: blocks [0, PREP_BLOCKS) precompute W12 = W1@W2 and bW = b1@W2.
//     Remaining blocks build the degree histogram (self-detecting dtype).
__global__ __launch_bounds__(256) void prep_hist_kernel(
    const int* __restrict__ ei32,
    const float* __restrict__ W1,
    const float* __restrict__ b1,
    const float* __restrict__ W2,
    int E)
{
    const int tid = threadIdx.x;

    if (blockIdx.x < PREP_BLOCKS) {
        // r in [0,64) -> row r of W12; r == 64 -> bW.  4-way k split + reduce.
        const int r  = blockIdx.x;
        const int j  = tid & 63;
        const int kc = tid >> 6;
        const float* src = (r < D_IN) ? (W1 + (size_t)r * D_HID) : b1;

        float a = 0.f;
        #pragma unroll 8
        for (int k = kc * 32; k < kc * 32 + 32; ++k)
            a = fmaf(src[k], W2[(size_t)k * D_OUT + j], a);

        __shared__ float red[4][64];
        red[kc][j] = a;
        __syncthreads();
        if (kc == 0) {
            float v = red[0][j] + red[1][j] + red[2][j] + red[3][j];
            if (r < D_IN) g_W12[r * D_OUT + j] = v;
            else          g_bW[j] = v;
        }
        return;
    }

    // ---- histogram over edge_index[1] (dst row) ----
    __shared__ int s_is64;
    if (tid == 0) {
        int is64 = 1;
        #pragma unroll
        for (int i = 1; i < 64; i += 2)
            if (ei32[i] != 0) is64 = 0;
        s_is64 = is64;
    }
    __syncthreads();

    const int hb = blockIdx.x - PREP_BLOCKS;
    const long long i0 = ((long long)hb * 256 + tid) * EPT;
    if (i0 >= E) return;

    if (s_is64) {
        const unsigned long long* p =
            (const unsigned long long*)ei32 + E;          // dst row (int64)
        if (i0 + EPT <= E) {
            const ulonglong2* q = (const ulonglong2*)(p + i0);
            #pragma unroll
            for (int c = 0; c < EPT / 2; ++c) {
                ulonglong2 v = q[c];
                atomicAdd(&g_deg[(int)v.x], 1);
                atomicAdd(&g_deg[(int)v.y], 1);
            }
        } else {
            for (long long j = i0; j < E; ++j) atomicAdd(&g_deg[(int)p[j]], 1);
        }
    } else {
        const int* p = (const int*)ei32 + E;              // dst row (int32)
        if (i0 + EPT <= E) {
            const int4* q = (const int4*)(p + i0);
            #pragma unroll
            for (int c = 0; c < EPT / 4; ++c) {
                int4 v = q[c];
                atomicAdd(&g_deg[v.x], 1); atomicAdd(&g_deg[v.y], 1);
                atomicAdd(&g_deg[v.z], 1); atomicAdd(&g_deg[v.w], 1);
            }
        } else {
            for (long long j = i0; j < E; ++j) atomicAdd(&g_deg[p[j]], 1);
        }
    }
}

// ---------------------------------------------------------------------------
// K2: out[n] = (1+deg[n]) * (x[n] @ W12 + bW) + b2, then deg[n] := 0.
// 256 threads / 256 nodes per block. Thread (g = tid>>2, q = tid&3) computes
// cols {16v + 4q .. 16v + 4q + 3 : v=0..3} for 4 nodes — bank-conflict-free
// weight LDS.128 (all 4 q's hit disjoint banks per v).
__global__ __launch_bounds__(256) void gnn_main_kernel(
    const float* __restrict__ x,
    const float* __restrict__ b2,
    float* __restrict__ out,
    int n)
{
    extern __shared__ float smem[];
    float* xs   = smem;                          // NPB * XS_STRIDE
    float* w12  = smem + NPB * XS_STRIDE;        // 64*64
    float* bw_s = w12 + D_IN * D_OUT;            // 64
    float* b2_s = bw_s + D_OUT;                  // 64

    const int tid  = threadIdx.x;
    const int base = blockIdx.x * NPB;

    for (int i = tid; i < D_IN * D_OUT / 4; i += 256)
        ((float4*)w12)[i] = ((const float4*)g_W12)[i];
    if (tid < D_OUT) { bw_s[tid] = g_bW[tid]; b2_s[tid] = b2[tid]; }

    #pragma unroll 4
    for (int i = tid; i < NPB * D_IN; i += 256) {
        int nl = i >> 6, c = i & 63;
        xs[nl * XS_STRIDE + c] =
            (base + nl < n) ? x[(size_t)(base + nl) * D_IN + c] : 0.f;
    }
    __syncthreads();

    const int q  = tid & 3;
    const int n0 = (tid >> 2) * 4;

    unsigned long long acc[4][8];
    #pragma unroll
    for (int i = 0; i < 4; ++i)
        #pragma unroll
        for (int j = 0; j < 8; ++j) acc[i][j] = 0ull;

    const float* wq = w12 + 4 * q;               // thread's base column

    #pragma unroll 8
    for (int k = 0; k < D_IN; ++k) {
        const float* wr = wq + k * D_OUT;
        ulonglong2 w0 = *(const ulonglong2*)(wr);        // cols 4q..4q+3
        ulonglong2 w1 = *(const ulonglong2*)(wr + 16);   // cols 16+4q..
        ulonglong2 w2 = *(const ulonglong2*)(wr + 32);   // cols 32+4q..
        ulonglong2 w3 = *(const ulonglong2*)(wr + 48);   // cols 48+4q..
        unsigned long long w[8] = {w0.x, w0.y, w1.x, w1.y,
                                   w2.x, w2.y, w3.x, w3.y};
        #pragma unroll
        for (int i = 0; i < 4; ++i) {
            unsigned long long xp = bcast2(xs[(n0 + i) * XS_STRIDE + k]);
            #pragma unroll
            for (int j = 0; j < 8; ++j) acc[i][j] = fma2(xp, w[j], acc[i][j]);
        }
    }

    // Epilogue: scale by (1+deg), add biases, store; reset deg for next call.
    #pragma unroll
    for (int i = 0; i < 4; ++i) {
        const int node = base + n0 + i;
        if (node >= n) break;
        const float s = 1.0f + (float)g_deg[node];
        if (q == 0) g_deg[node] = 0;             // consume-reset
        #pragma unroll
        for (int v = 0; v < 4; ++v) {
            const int c = v * 16 + 4 * q;
            float lo0, hi0, lo1, hi1;
            unpack2(acc[i][2 * v],     lo0, hi0);
            unpack2(acc[i][2 * v + 1], lo1, hi1);
            float4 r;
            r.x = fmaf(s, lo0 + bw_s[c + 0], b2_s[c + 0]);
            r.y = fmaf(s, hi0 + bw_s[c + 1], b2_s[c + 1]);
            r.z = fmaf(s, lo1 + bw_s[c + 2], b2_s[c + 2]);
            r.w = fmaf(s, hi1 + bw_s[c + 3], b2_s[c + 3]);
            *(float4*)(out + (size_t)node * D_OUT + c) = r;
        }
    }
}

// ---------------------------------------------------------------------------
extern "C" void kernel_launch(void* const* d_in, const int* in_sizes, int n_in,
                              void* d_out, int out_size) {
    const float* x  = (const float*)d_in[0];
    const void*  ei = d_in[1];
    const float* W1 = (const float*)d_in[2];
    const float* b1 = (const float*)d_in[3];
    const float* W2 = (const float*)d_in[4];
    const float* b2 = (const float*)d_in[5];
    float* out = (float*)d_out;

    const int n = in_sizes[0] / D_IN;   // 100000
    const int E = in_sizes[1] / 2;      // 1000000

    const int hist_blocks = (E + 256 * EPT - 1) / (256 * EPT);
    prep_hist_kernel<<<PREP_BLOCKS + hist_blocks, 256>>>(
        (const int*)ei, W1, b1, W2, E);

    const size_t smem_bytes =
        (NPB * XS_STRIDE + D_IN * D_OUT + 2 * D_OUT) * sizeof(float);
    cudaFuncSetAttribute(gnn_main_kernel,
                         cudaFuncAttributeMaxDynamicSharedMemorySize,
                         (int)smem_bytes);
    gnn_main_kernel<<<(n + NPB - 1) / NPB, 256, smem_bytes>>>(x, b2, out, n);
}

// round 4
// speedup vs baseline: 3.3747x; 1.3650x over previous
#include <cuda_runtime.h>

#define D_IN   64
#define D_OUT  64
#define D_HID  128
#define MAX_NODES 100000
#define NPB    128                 // nodes per block in main kernel
#define NT     128                 // threads per block in main kernel
#define XS_STRIDE 65               // padded row stride for xs (conflict-free)
#define PREP_BLOCKS 65             // W12 rows + bW
#define EPT    8                   // edges per thread in hist

// Scratch. g_deg relies on the consume-reset invariant: zero at module load,
// gnn_main_kernel resets each entry after reading it.
__device__ int   g_deg[MAX_NODES];
__device__ float g_W12[D_IN * D_OUT];
__device__ float g_bW[D_OUT];

// ---------------------------------------------------------------------------
// Packed f32x2 helpers (sm_103a FFMA2 path)
__device__ __forceinline__ unsigned long long fma2(unsigned long long a,
                                                   unsigned long long b,
                                                   unsigned long long c) {
    unsigned long long d;
    asm("fma.rn.f32x2 %0, %1, %2, %3;" : "=l"(d) : "l"(a), "l"(b), "l"(c));
    return d;
}
__device__ __forceinline__ unsigned long long bcast2(float x) {
    unsigned int xi = __float_as_uint(x);
    unsigned long long d;
    asm("mov.b64 %0, {%1, %1};" : "=l"(d) : "r"(xi));
    return d;
}
__device__ __forceinline__ void unpack2(unsigned long long v, float& lo, float& hi) {
    unsigned int a, b;
    asm("mov.b64 {%0, %1}, %2;" : "=r"(a), "=r"(b) : "l"(v));
    lo = __uint_as_float(a); hi = __uint_as_float(b);
}

// ---------------------------------------------------------------------------
// K1: blocks [0, PREP_BLOCKS) precompute W12 = W1@W2 and bW = b1@W2.
//     Remaining blocks build the degree histogram (self-detecting dtype).
__global__ __launch_bounds__(256) void prep_hist_kernel(
    const int* __restrict__ ei32,
    const float* __restrict__ W1,
    const float* __restrict__ b1,
    const float* __restrict__ W2,
    int E)
{
    const int tid = threadIdx.x;

    if (blockIdx.x < PREP_BLOCKS) {
        const int r  = blockIdx.x;
        const int j  = tid & 63;
        const int kc = tid >> 6;
        const float* src = (r < D_IN) ? (W1 + (size_t)r * D_HID) : b1;

        float a = 0.f;
        #pragma unroll 8
        for (int k = kc * 32; k < kc * 32 + 32; ++k)
            a = fmaf(src[k], W2[(size_t)k * D_OUT + j], a);

        __shared__ float red[4][64];
        red[kc][j] = a;
        __syncthreads();
        if (kc == 0) {
            float v = red[0][j] + red[1][j] + red[2][j] + red[3][j];
            if (r < D_IN) g_W12[r * D_OUT + j] = v;
            else          g_bW[j] = v;
        }
        return;
    }

    // ---- histogram over edge_index[1] (dst row) ----
    __shared__ int s_is64;
    if (tid == 0) {
        int is64 = 1;
        #pragma unroll
        for (int i = 1; i < 64; i += 2)
            if (ei32[i] != 0) is64 = 0;
        s_is64 = is64;
    }
    __syncthreads();

    const int hb = blockIdx.x - PREP_BLOCKS;
    const long long i0 = ((long long)hb * 256 + tid) * EPT;
    if (i0 >= E) return;

    if (s_is64) {
        const unsigned long long* p = (const unsigned long long*)ei32 + E;
        if (i0 + EPT <= E) {
            const ulonglong2* q = (const ulonglong2*)(p + i0);
            #pragma unroll
            for (int c = 0; c < EPT / 2; ++c) {
                ulonglong2 v = q[c];
                atomicAdd(&g_deg[(int)v.x], 1);
                atomicAdd(&g_deg[(int)v.y], 1);
            }
        } else {
            for (long long j = i0; j < E; ++j) atomicAdd(&g_deg[(int)p[j]], 1);
        }
    } else {
        const int* p = (const int*)ei32 + E;
        if (i0 + EPT <= E) {
            const int4* q = (const int4*)(p + i0);
            #pragma unroll
            for (int c = 0; c < EPT / 4; ++c) {
                int4 v = q[c];
                atomicAdd(&g_deg[v.x], 1); atomicAdd(&g_deg[v.y], 1);
                atomicAdd(&g_deg[v.z], 1); atomicAdd(&g_deg[v.w], 1);
            }
        } else {
            for (long long j = i0; j < E; ++j) atomicAdd(&g_deg[p[j]], 1);
        }
    }
}

// ---------------------------------------------------------------------------
// K2: out[n] = (1+deg[n]) * (x[n] @ W12 + bW) + b2, then deg[n] := 0.
// 128 threads / 128 nodes per block, 4 blocks/SM. Thread (g = tid>>2, q=tid&3)
// computes cols {16v + 4q .. +3 : v=0..3} for 4 nodes via packed f32x2 FMA.
__global__ __launch_bounds__(NT, 4) void gnn_main_kernel(
    const float* __restrict__ x,
    const float* __restrict__ b2,
    float* __restrict__ out,
    int n)
{
    extern __shared__ float smem[];
    float* xs   = smem;                          // NPB * XS_STRIDE
    float* w12  = smem + NPB * XS_STRIDE;        // 64*64
    float* bw_s = w12 + D_IN * D_OUT;            // 64
    float* b2_s = bw_s + D_OUT;                  // 64

    const int tid  = threadIdx.x;
    const int base = blockIdx.x * NPB;
    const int q    = tid & 3;
    const int n0   = (tid >> 2) * 4;

    // Early degree prefetch: scattered-ish LDGs issued before the FMA loop so
    // their latency hides under compute.
    int deg[4];
    #pragma unroll
    for (int i = 0; i < 4; ++i) {
        const int node = base + n0 + i;
        deg[i] = (node < n) ? g_deg[node] : 0;
    }

    // Stage W12 (1024 float4 / 128 threads = 8 each) + biases
    #pragma unroll
    for (int i = tid; i < D_IN * D_OUT / 4; i += NT)
        ((float4*)w12)[i] = ((const float4*)g_W12)[i];
    if (tid < D_OUT) { bw_s[tid] = g_bW[tid]; b2_s[tid] = b2[tid]; }

    // Stage x tile: LDG.128 + 4 scalar STS into padded rows (conflict-free).
    const bool full = (base + NPB <= n);
    #pragma unroll
    for (int idx = tid; idx < NPB * D_IN / 4; idx += NT) {
        const int nl = idx >> 4;            // local node
        const int c  = (idx & 15) * 4;      // column base
        float4 v;
        if (full || base + nl < n) v = *(const float4*)(x + (size_t)(base + nl) * D_IN + c);
        else                       v = make_float4(0.f, 0.f, 0.f, 0.f);
        float* dst = xs + nl * XS_STRIDE + c;
        dst[0] = v.x; dst[1] = v.y; dst[2] = v.z; dst[3] = v.w;
    }
    __syncthreads();

    unsigned long long acc[4][8];
    #pragma unroll
    for (int i = 0; i < 4; ++i)
        #pragma unroll
        for (int j = 0; j < 8; ++j) acc[i][j] = 0ull;

    const float* wq = w12 + 4 * q;

    #pragma unroll 8
    for (int k = 0; k < D_IN; ++k) {
        const float* wr = wq + k * D_OUT;
        ulonglong2 w0 = *(const ulonglong2*)(wr);
        ulonglong2 w1 = *(const ulonglong2*)(wr + 16);
        ulonglong2 w2 = *(const ulonglong2*)(wr + 32);
        ulonglong2 w3 = *(const ulonglong2*)(wr + 48);
        unsigned long long w[8] = {w0.x, w0.y, w1.x, w1.y,
                                   w2.x, w2.y, w3.x, w3.y};
        #pragma unroll
        for (int i = 0; i < 4; ++i) {
            unsigned long long xp = bcast2(xs[(n0 + i) * XS_STRIDE + k]);
            #pragma unroll
            for (int j = 0; j < 8; ++j) acc[i][j] = fma2(xp, w[j], acc[i][j]);
        }
    }

    // Epilogue: scale by (1+deg), add biases, store; reset deg for next call.
    #pragma unroll
    for (int i = 0; i < 4; ++i) {
        const int node = base + n0 + i;
        if (node >= n) break;
        const float s = 1.0f + (float)deg[i];
        if (q == 0) g_deg[node] = 0;             // consume-reset
        #pragma unroll
        for (int v = 0; v < 4; ++v) {
            const int c = v * 16 + 4 * q;
            float lo0, hi0, lo1, hi1;
            unpack2(acc[i][2 * v],     lo0, hi0);
            unpack2(acc[i][2 * v + 1], lo1, hi1);
            float4 r;
            r.x = fmaf(s, lo0 + bw_s[c + 0], b2_s[c + 0]);
            r.y = fmaf(s, hi0 + bw_s[c + 1], b2_s[c + 1]);
            r.z = fmaf(s, lo1 + bw_s[c + 2], b2_s[c + 2]);
            r.w = fmaf(s, hi1 + bw_s[c + 3], b2_s[c + 3]);
            *(float4*)(out + (size_t)node * D_OUT + c) = r;
        }
    }
}

// ---------------------------------------------------------------------------
extern "C" void kernel_launch(void* const* d_in, const int* in_sizes, int n_in,
                              void* d_out, int out_size) {
    const float* x  = (const float*)d_in[0];
    const void*  ei = d_in[1];
    const float* W1 = (const float*)d_in[2];
    const float* b1 = (const float*)d_in[3];
    const float* W2 = (const float*)d_in[4];
    const float* b2 = (const float*)d_in[5];
    float* out = (float*)d_out;

    const int n = in_sizes[0] / D_IN;   // 100000
    const int E = in_sizes[1] / 2;      // 1000000

    const int hist_blocks = (E + 256 * EPT - 1) / (256 * EPT);
    prep_hist_kernel<<<PREP_BLOCKS + hist_blocks, 256>>>(
        (const int*)ei, W1, b1, W2, E);

    const size_t smem_bytes =
        (NPB * XS_STRIDE + D_IN * D_OUT + 2 * D_OUT) * sizeof(float);
    cudaFuncSetAttribute(gnn_main_kernel,
                         cudaFuncAttributeMaxDynamicSharedMemorySize,
                         (int)smem_bytes);
    gnn_main_kernel<<<(n + NPB - 1) / NPB, NT, smem_bytes>>>(x, b2, out, n);
}